// round 11
// baseline (speedup 1.0000x reference)
#include <cuda_runtime.h>
#include <math.h>

// Problem constants (fixed by setup_inputs)
#define BB 64
#define LL 512
#define NNCH 64
#define AAA 64
#define DDD 256
#define PPP 16

// Scratch (no cudaMalloc allowed). conv partials: [b][slab(8)][o(32)]
__device__ float g_partial[BB * 8 * 32];

// -------- packed fp32x2 ops (Blackwell) --------
__device__ __forceinline__ void fma2(unsigned long long& c, unsigned long long a,
                                     unsigned long long b) {
    asm("fma.rn.f32x2 %0, %1, %2, %0;" : "+l"(c) : "l"(a), "l"(b));
}
__device__ __forceinline__ unsigned long long mul2(unsigned long long a,
                                                   unsigned long long b) {
    unsigned long long r;
    asm("mul.rn.f32x2 %0, %1, %2;" : "=l"(r) : "l"(a), "l"(b));
    return r;
}
__device__ __forceinline__ ulonglong2 as_ull2(float4 v) {
    return *reinterpret_cast<ulonglong2*>(&v);
}
__device__ __forceinline__ float2 as_f2(unsigned long long v) {
    return *reinterpret_cast<float2*>(&v);
}
__device__ __forceinline__ unsigned long long pack2(float lo, float hi) {
    unsigned long long r;
    asm("mov.b64 %0, {%1, %2};" : "=l"(r) : "f"(lo), "f"(hi));
    return r;
}

// ============================================================================
// Kernel 1: Conv1d(N->32, k=3, pad=1) -> ReLU -> partial sum over a 64-l slab.
// grid (8, B). 256 threads (8 warps). Warp w owns channels 4w..4w+3.
// (unchanged from R10 measured build)
// ============================================================================
__global__ __launch_bounds__(256) void conv_pool_kernel(
    const float* __restrict__ x, const float* __restrict__ conv_w,
    const float* __restrict__ conv_b) {
    __shared__ float4 sx4[34 * 17];      // pitch 17 float4 -> conflict-free
    __shared__ float4 sw4[32 * 3 * 16];  // [o][k][i] layout, broadcast reads

    const int t = threadIdx.x;
    const int h = blockIdx.x, b = blockIdx.y;

    for (int u = t; u < 32 * 64 * 3; u += 256) {
        int o = u / 192;
        int rem = u % 192;
        int i = rem / 3;
        int k = rem % 3;
        reinterpret_cast<float*>(sw4)[(o * 3 + k) * 64 + i] = conv_w[u];
    }

    const int w = t >> 5, lane = t & 31;
    const int o0 = w * 4;
    const float cb0 = conv_b[o0 + 0], cb1 = conv_b[o0 + 1];
    const float cb2 = conv_b[o0 + 2], cb3 = conv_b[o0 + 3];
    float pool0 = 0.f, pool1 = 0.f, pool2 = 0.f, pool3 = 0.f;
    const float4* x4 = reinterpret_cast<const float4*>(x);

    for (int tile = 0; tile < 2; tile++) {
        const int row0 = h * 64 + tile * 32 - 1;
        __syncthreads();
        for (int u = t; u < 34 * 16; u += 256) {
            int r = u >> 4, i4 = u & 15;
            int gr = row0 + r;
            float4 v = make_float4(0.f, 0.f, 0.f, 0.f);
            if (gr >= 0 && gr < LL) v = x4[(b * LL + gr) * 16 + i4];
            sx4[r * 17 + i4] = v;
        }
        __syncthreads();

        unsigned long long acc0 = 0ull, acc1 = 0ull, acc2 = 0ull, acc3 = 0ull;
#pragma unroll
        for (int k = 0; k < 3; k++) {
#pragma unroll
            for (int i4 = 0; i4 < 16; i4++) {
                float4 xv = sx4[(lane + k) * 17 + i4];
                ulonglong2 xp = as_ull2(xv);
                float4 wv0 = sw4[((o0 + 0) * 3 + k) * 16 + i4];
                float4 wv1 = sw4[((o0 + 1) * 3 + k) * 16 + i4];
                float4 wv2 = sw4[((o0 + 2) * 3 + k) * 16 + i4];
                float4 wv3 = sw4[((o0 + 3) * 3 + k) * 16 + i4];
                ulonglong2 w0 = as_ull2(wv0), w1 = as_ull2(wv1);
                ulonglong2 w2 = as_ull2(wv2), w3 = as_ull2(wv3);
                fma2(acc0, xp.x, w0.x);
                fma2(acc0, xp.y, w0.y);
                fma2(acc1, xp.x, w1.x);
                fma2(acc1, xp.y, w1.y);
                fma2(acc2, xp.x, w2.x);
                fma2(acc2, xp.y, w2.y);
                fma2(acc3, xp.x, w3.x);
                fma2(acc3, xp.y, w3.y);
            }
        }
        {
            float2 a0 = as_f2(acc0), a1 = as_f2(acc1), a2 = as_f2(acc2), a3 = as_f2(acc3);
            pool0 += fmaxf(a0.x + a0.y + cb0, 0.f);
            pool1 += fmaxf(a1.x + a1.y + cb1, 0.f);
            pool2 += fmaxf(a2.x + a2.y + cb2, 0.f);
            pool3 += fmaxf(a3.x + a3.y + cb3, 0.f);
        }
    }

#pragma unroll
    for (int off = 16; off > 0; off >>= 1) {
        pool0 += __shfl_xor_sync(0xffffffffu, pool0, off);
        pool1 += __shfl_xor_sync(0xffffffffu, pool1, off);
        pool2 += __shfl_xor_sync(0xffffffffu, pool2, off);
        pool3 += __shfl_xor_sync(0xffffffffu, pool3, off);
    }
    if (lane == 0) {
        float* dst = g_partial + (b * 8 + h) * 32 + o0;
        dst[0] = pool0;
        dst[1] = pool1;
        dst[2] = pool2;
        dst[3] = pool3;
    }
}

// ============================================================================
// Kernel 2 v3: p-parity-pair accumulation (zero dup MOVs) + samp prefetch.
// grid (A/2, B, 2). 256 threads, 8 warps. Thread owns 4 d-cols
// (d0 = (w&1)*128 + lane*4); warp pair q=w>>1 does rows q*8..q*8+7, both
// anchors. acc_j = (sum even-p, sum odd-p) for col d0+j; samp pairs come free
// from LDS.128 reinterpret; weight pairs built once at preload.
// ============================================================================
__global__ __launch_bounds__(256, 2) void patch_kernel(
    const float* __restrict__ x, const float* __restrict__ lin_w,
    const float* __restrict__ lin_b, const float* __restrict__ wp_w,
    const float* __restrict__ wp_b, float* __restrict__ out) {
    __shared__ float s_wpT[PPP][DDD + 4];  // transposed [p][d], pitch 260
    __shared__ float s_samp[2][32][20];    // [ai][n][p], pitch 20 (16B-aligned)
    __shared__ float s_delta[2];

    const int t = threadIdx.x;
    const int a0 = blockIdx.x * 2, b = blockIdx.y, h = blockIdx.z;
    const int w = t >> 5, lane = t & 31;
    const int dh = w & 1;
    const int q = w >> 1;
    const int d0 = dh * 128 + lane * 4;

    // ---- stage wp_w (D,P) -> s_wpT[p][d], coalesced LDG.128 ----
    {
        const float4* wpw4 = reinterpret_cast<const float4*>(wp_w);
#pragma unroll
        for (int c = 0; c < 4; c++) {
            int u4 = t + 256 * c;  // 0..1023
            float4 v = wpw4[u4];   // = wp_w[d][p0..p0+3], d=u4>>2, p0=(u4&3)*4
            int d = u4 >> 2, p0 = (u4 & 3) * 4;
            s_wpT[p0 + 0][d] = v.x;
            s_wpT[p0 + 1][d] = v.y;
            s_wpT[p0 + 2][d] = v.z;
            s_wpT[p0 + 3][d] = v.w;
        }
    }

    // ---- warps 0,1: delta(b, a0+w) ----
    if (w < 2) {
        const int a = a0 + w;
        float pooled = 0.f;
#pragma unroll
        for (int s = 0; s < 8; s++) pooled += g_partial[(b * 8 + s) * 32 + lane];
        pooled *= (1.0f / 512.0f);
        float term = pooled * lin_w[a * 32 + lane];
#pragma unroll
        for (int off = 16; off > 0; off >>= 1)
            term += __shfl_xor_sync(0xffffffffu, term, off);
        if (lane == 0) s_delta[w] = 4.0f * tanhf(term + lin_b[a]);
    }

    float4 bias = reinterpret_cast<const float4*>(wp_b)[d0 >> 2];  // coalesced
    __syncthreads();  // s_wpT + s_delta ready

    // ---- weight pairs over p: wppJ[k] = (w[d0+J][2k], w[d0+J][2k+1]) ----
    // built from 16 conflict-free LDS.128 + one-time packs
    unsigned long long wpp0[8], wpp1[8], wpp2[8], wpp3[8];
#pragma unroll
    for (int k = 0; k < 8; k++) {
        float4 we = *reinterpret_cast<const float4*>(&s_wpT[2 * k + 0][d0]);
        float4 wo = *reinterpret_cast<const float4*>(&s_wpT[2 * k + 1][d0]);
        wpp0[k] = pack2(we.x, wo.x);
        wpp1[k] = pack2(we.y, wo.y);
        wpp2[k] = pack2(we.z, wo.z);
        wpp3[k] = pack2(we.w, wo.w);
    }

    // ---- bilinear sampling: thread owns (ai, p4-group, n) -> one STS.128 ----
    {
        const int nl = t & 31;
        const int n = h * 32 + nl;
        const int g = t >> 5;       // 0..7
        const int ai = g >> 2;      // 0..1
        const int p4 = g & 3;       // 0..3
        const float* xb = x + (size_t)b * LL * NNCH;
        const float base = (float)((a0 + ai) * 8) + s_delta[ai] - 7.5f;
        float vals[4];
#pragma unroll
        for (int j = 0; j < 4; j++) {
            int p = p4 * 4 + j;
            float xs = base + (float)p;
            xs = fminf(fmaxf(xs, 0.f), 511.f);
            float fl = floorf(xs);
            int i0 = (int)fl;
            float f = xs - fl;
            int i1 = min(i0 + 1, LL - 1);
            vals[j] = xb[i0 * NNCH + n] * (1.0f - f) + xb[i1 * NNCH + n] * f;
        }
        *reinterpret_cast<float4*>(&s_samp[ai][nl][p4 * 4]) =
            make_float4(vals[0], vals[1], vals[2], vals[3]);
    }
    __syncthreads();

    // ---- mainloop: 16 (row, anchor) combos, software-prefetched samp ----
    float4 sa, sb, sc, sd;
    {
        const float* sp = &s_samp[0][q * 8][0];
        sa = *reinterpret_cast<const float4*>(sp + 0);
        sb = *reinterpret_cast<const float4*>(sp + 4);
        sc = *reinterpret_cast<const float4*>(sp + 8);
        sd = *reinterpret_cast<const float4*>(sp + 12);
    }
#pragma unroll 1
    for (int c = 0; c < 16; c++) {
        // snapshot current combo's samp
        const float4 ca = sa, cb = sb, cc = sc, cd = sd;
        // prefetch next combo
        if (c < 15) {
            const int cn = c + 1;
            const int ain = cn >> 3;
            const int rown = q * 8 + (cn & 7);
            const float* spn = &s_samp[ain][rown][0];
            sa = *reinterpret_cast<const float4*>(spn + 0);
            sb = *reinterpret_cast<const float4*>(spn + 4);
            sc = *reinterpret_cast<const float4*>(spn + 8);
            sd = *reinterpret_cast<const float4*>(spn + 12);
        }

        ulonglong2 A = *reinterpret_cast<const ulonglong2*>(&ca);
        ulonglong2 B = *reinterpret_cast<const ulonglong2*>(&cb);
        ulonglong2 C = *reinterpret_cast<const ulonglong2*>(&cc);
        ulonglong2 D = *reinterpret_cast<const ulonglong2*>(&cd);

        // k=0 via mul (defines acc, no bias-init movs)
        unsigned long long acc0 = mul2(A.x, wpp0[0]);
        unsigned long long acc1 = mul2(A.x, wpp1[0]);
        unsigned long long acc2 = mul2(A.x, wpp2[0]);
        unsigned long long acc3 = mul2(A.x, wpp3[0]);
#define QSTEP(sp2, k)        \
    fma2(acc0, sp2, wpp0[k]); \
    fma2(acc1, sp2, wpp1[k]); \
    fma2(acc2, sp2, wpp2[k]); \
    fma2(acc3, sp2, wpp3[k]);
        QSTEP(A.y, 1)
        QSTEP(B.x, 2)
        QSTEP(B.y, 3)
        QSTEP(C.x, 4)
        QSTEP(C.y, 5)
        QSTEP(D.x, 6)
        QSTEP(D.y, 7)
#undef QSTEP

        const int ai = c >> 3;
        const int row = q * 8 + (c & 7);
        const int n = h * 32 + row;
        float* op =
            out + (((size_t)(b * 64 + n) * 64 + (a0 + ai)) * 256) + d0;
        float2 r0 = as_f2(acc0), r1 = as_f2(acc1);
        float2 r2 = as_f2(acc2), r3 = as_f2(acc3);
        __stcs(reinterpret_cast<float4*>(op),
               make_float4(r0.x + r0.y + bias.x, r1.x + r1.y + bias.y,
                           r2.x + r2.y + bias.z, r3.x + r3.y + bias.w));
    }
}

// ============================================================================
extern "C" void kernel_launch(void* const* d_in, const int* in_sizes, int n_in,
                              void* d_out, int out_size) {
    const float* x = (const float*)d_in[0];
    const float* conv_w = (const float*)d_in[1];
    const float* conv_b = (const float*)d_in[2];
    const float* lin_w = (const float*)d_in[3];
    const float* lin_b = (const float*)d_in[4];
    const float* wp_w = (const float*)d_in[5];
    const float* wp_b = (const float*)d_in[6];

    conv_pool_kernel<<<dim3(8, BB), 256>>>(x, conv_w, conv_b);
    patch_kernel<<<dim3(AAA / 2, BB, 2), 256>>>(x, lin_w, lin_b, wp_w, wp_b,
                                                (float*)d_out);
}

// round 14
// speedup vs baseline: 1.0297x; 1.0297x over previous
#include <cuda_runtime.h>
#include <math.h>

// Problem constants (fixed by setup_inputs)
#define BB 64
#define LL 512
#define NNCH 64
#define AAA 64
#define DDD 256
#define PPP 16

// Scratch (no cudaMalloc allowed). conv partials: [b][slab(8)][o(32)]
__device__ float g_partial[BB * 8 * 32];

// -------- packed fp32x2 ops (Blackwell) --------
__device__ __forceinline__ void fma2(unsigned long long& c, unsigned long long a,
                                     unsigned long long b) {
    asm("fma.rn.f32x2 %0, %1, %2, %0;" : "+l"(c) : "l"(a), "l"(b));
}
__device__ __forceinline__ unsigned long long mul2(unsigned long long a,
                                                   unsigned long long b) {
    unsigned long long r;
    asm("mul.rn.f32x2 %0, %1, %2;" : "=l"(r) : "l"(a), "l"(b));
    return r;
}
__device__ __forceinline__ ulonglong2 as_ull2(float4 v) {
    return *reinterpret_cast<ulonglong2*>(&v);
}
__device__ __forceinline__ float2 as_f2(unsigned long long v) {
    return *reinterpret_cast<float2*>(&v);
}
__device__ __forceinline__ unsigned long long pack2(float lo, float hi) {
    unsigned long long r;
    asm("mov.b64 %0, {%1, %2};" : "=l"(r) : "f"(lo), "f"(hi));
    return r;
}

// ============================================================================
// Kernel 1: Conv1d(N->32, k=3, pad=1) -> ReLU -> partial sum over a 64-l slab.
// grid (8, B). 256 threads (8 warps). Warp w owns channels 4w..4w+3.
// (unchanged from R10 measured build)
// ============================================================================
__global__ __launch_bounds__(256) void conv_pool_kernel(
    const float* __restrict__ x, const float* __restrict__ conv_w,
    const float* __restrict__ conv_b) {
    __shared__ float4 sx4[34 * 17];      // pitch 17 float4 -> conflict-free
    __shared__ float4 sw4[32 * 3 * 16];  // [o][k][i] layout, broadcast reads

    const int t = threadIdx.x;
    const int h = blockIdx.x, b = blockIdx.y;

    for (int u = t; u < 32 * 64 * 3; u += 256) {
        int o = u / 192;
        int rem = u % 192;
        int i = rem / 3;
        int k = rem % 3;
        reinterpret_cast<float*>(sw4)[(o * 3 + k) * 64 + i] = conv_w[u];
    }

    const int w = t >> 5, lane = t & 31;
    const int o0 = w * 4;
    const float cb0 = conv_b[o0 + 0], cb1 = conv_b[o0 + 1];
    const float cb2 = conv_b[o0 + 2], cb3 = conv_b[o0 + 3];
    float pool0 = 0.f, pool1 = 0.f, pool2 = 0.f, pool3 = 0.f;
    const float4* x4 = reinterpret_cast<const float4*>(x);

    for (int tile = 0; tile < 2; tile++) {
        const int row0 = h * 64 + tile * 32 - 1;
        __syncthreads();
        for (int u = t; u < 34 * 16; u += 256) {
            int r = u >> 4, i4 = u & 15;
            int gr = row0 + r;
            float4 v = make_float4(0.f, 0.f, 0.f, 0.f);
            if (gr >= 0 && gr < LL) v = x4[(b * LL + gr) * 16 + i4];
            sx4[r * 17 + i4] = v;
        }
        __syncthreads();

        unsigned long long acc0 = 0ull, acc1 = 0ull, acc2 = 0ull, acc3 = 0ull;
#pragma unroll
        for (int k = 0; k < 3; k++) {
#pragma unroll
            for (int i4 = 0; i4 < 16; i4++) {
                float4 xv = sx4[(lane + k) * 17 + i4];
                ulonglong2 xp = as_ull2(xv);
                float4 wv0 = sw4[((o0 + 0) * 3 + k) * 16 + i4];
                float4 wv1 = sw4[((o0 + 1) * 3 + k) * 16 + i4];
                float4 wv2 = sw4[((o0 + 2) * 3 + k) * 16 + i4];
                float4 wv3 = sw4[((o0 + 3) * 3 + k) * 16 + i4];
                ulonglong2 w0 = as_ull2(wv0), w1 = as_ull2(wv1);
                ulonglong2 w2 = as_ull2(wv2), w3 = as_ull2(wv3);
                fma2(acc0, xp.x, w0.x);
                fma2(acc0, xp.y, w0.y);
                fma2(acc1, xp.x, w1.x);
                fma2(acc1, xp.y, w1.y);
                fma2(acc2, xp.x, w2.x);
                fma2(acc2, xp.y, w2.y);
                fma2(acc3, xp.x, w3.x);
                fma2(acc3, xp.y, w3.y);
            }
        }
        {
            float2 a0 = as_f2(acc0), a1 = as_f2(acc1), a2 = as_f2(acc2), a3 = as_f2(acc3);
            pool0 += fmaxf(a0.x + a0.y + cb0, 0.f);
            pool1 += fmaxf(a1.x + a1.y + cb1, 0.f);
            pool2 += fmaxf(a2.x + a2.y + cb2, 0.f);
            pool3 += fmaxf(a3.x + a3.y + cb3, 0.f);
        }
    }

#pragma unroll
    for (int off = 16; off > 0; off >>= 1) {
        pool0 += __shfl_xor_sync(0xffffffffu, pool0, off);
        pool1 += __shfl_xor_sync(0xffffffffu, pool1, off);
        pool2 += __shfl_xor_sync(0xffffffffu, pool2, off);
        pool3 += __shfl_xor_sync(0xffffffffu, pool3, off);
    }
    if (lane == 0) {
        float* dst = g_partial + (b * 8 + h) * 32 + o0;
        dst[0] = pool0;
        dst[1] = pool1;
        dst[2] = pool2;
        dst[3] = pool3;
    }
}

// ============================================================================
// Kernel 2 v4: parity-pair accumulation, NO prefetch (R11's snapshot copies
// re-added the MOVs the repack removed). Direct LDS.128 -> packed math.
// grid (A/2, B, 2). 256 threads, 8 warps. Thread owns 4 d-cols
// (d0 = (w&1)*128 + lane*4); warp pair q=w>>1 does rows q*8..q*8+7, both
// anchors. acc_j = (sum even-p, sum odd-p) for col d0+j.
// Per combo: 4 LDS.128 + 4 MUL2 + 28 FFMA2 + 8 FADD + 1 STG.128.
// ============================================================================
__global__ __launch_bounds__(256, 2) void patch_kernel(
    const float* __restrict__ x, const float* __restrict__ lin_w,
    const float* __restrict__ lin_b, const float* __restrict__ wp_w,
    const float* __restrict__ wp_b, float* __restrict__ out) {
    __shared__ float s_wpT[PPP][DDD + 4];  // transposed [p][d], pitch 260
    __shared__ float s_samp[2][32][20];    // [ai][n][p], pitch 20 (16B-aligned)
    __shared__ float s_delta[2];

    const int t = threadIdx.x;
    const int a0 = blockIdx.x * 2, b = blockIdx.y, h = blockIdx.z;
    const int w = t >> 5, lane = t & 31;
    const int dh = w & 1;
    const int q = w >> 1;
    const int d0 = dh * 128 + lane * 4;

    // ---- stage wp_w (D,P) -> s_wpT[p][d], coalesced LDG.128 ----
    {
        const float4* wpw4 = reinterpret_cast<const float4*>(wp_w);
#pragma unroll
        for (int c = 0; c < 4; c++) {
            int u4 = t + 256 * c;  // 0..1023
            float4 v = wpw4[u4];   // = wp_w[d][p0..p0+3], d=u4>>2, p0=(u4&3)*4
            int d = u4 >> 2, p0 = (u4 & 3) * 4;
            s_wpT[p0 + 0][d] = v.x;
            s_wpT[p0 + 1][d] = v.y;
            s_wpT[p0 + 2][d] = v.z;
            s_wpT[p0 + 3][d] = v.w;
        }
    }

    // ---- warps 0,1: delta(b, a0+w) ----
    if (w < 2) {
        const int a = a0 + w;
        float pooled = 0.f;
#pragma unroll
        for (int s = 0; s < 8; s++) pooled += g_partial[(b * 8 + s) * 32 + lane];
        pooled *= (1.0f / 512.0f);
        float term = pooled * lin_w[a * 32 + lane];
#pragma unroll
        for (int off = 16; off > 0; off >>= 1)
            term += __shfl_xor_sync(0xffffffffu, term, off);
        if (lane == 0) s_delta[w] = 4.0f * tanhf(term + lin_b[a]);
    }

    float4 bias = reinterpret_cast<const float4*>(wp_b)[d0 >> 2];  // coalesced
    __syncthreads();  // s_wpT + s_delta ready

    // ---- weight pairs over p: wppJ[k] = (w[d0+J][2k], w[d0+J][2k+1]) ----
    // built from 16 conflict-free LDS.128 + one-time packs
    unsigned long long wpp0[8], wpp1[8], wpp2[8], wpp3[8];
#pragma unroll
    for (int k = 0; k < 8; k++) {
        float4 we = *reinterpret_cast<const float4*>(&s_wpT[2 * k + 0][d0]);
        float4 wo = *reinterpret_cast<const float4*>(&s_wpT[2 * k + 1][d0]);
        wpp0[k] = pack2(we.x, wo.x);
        wpp1[k] = pack2(we.y, wo.y);
        wpp2[k] = pack2(we.z, wo.z);
        wpp3[k] = pack2(we.w, wo.w);
    }

    // ---- bilinear sampling: thread owns (ai, p4-group, n) -> one STS.128 ----
    {
        const int nl = t & 31;
        const int n = h * 32 + nl;
        const int g = t >> 5;       // 0..7
        const int ai = g >> 2;      // 0..1
        const int p4 = g & 3;       // 0..3
        const float* xb = x + (size_t)b * LL * NNCH;
        const float base = (float)((a0 + ai) * 8) + s_delta[ai] - 7.5f;
        float vals[4];
#pragma unroll
        for (int j = 0; j < 4; j++) {
            int p = p4 * 4 + j;
            float xs = base + (float)p;
            xs = fminf(fmaxf(xs, 0.f), 511.f);
            float fl = floorf(xs);
            int i0 = (int)fl;
            float f = xs - fl;
            int i1 = min(i0 + 1, LL - 1);
            vals[j] = xb[i0 * NNCH + n] * (1.0f - f) + xb[i1 * NNCH + n] * f;
        }
        *reinterpret_cast<float4*>(&s_samp[ai][nl][p4 * 4]) =
            make_float4(vals[0], vals[1], vals[2], vals[3]);
    }
    __syncthreads();

    // ---- mainloop: 16 (row, anchor) combos, direct LDS -> packed math ----
#pragma unroll 1
    for (int c = 0; c < 16; c++) {
        const int ai = c >> 3;
        const int row = q * 8 + (c & 7);
        const float* sp = &s_samp[ai][row][0];
        float4 f0 = *reinterpret_cast<const float4*>(sp + 0);
        float4 f1 = *reinterpret_cast<const float4*>(sp + 4);
        float4 f2 = *reinterpret_cast<const float4*>(sp + 8);
        float4 f3 = *reinterpret_cast<const float4*>(sp + 12);
        ulonglong2 A = as_ull2(f0);  // (s0,s1),(s2,s3)
        ulonglong2 B = as_ull2(f1);
        ulonglong2 C = as_ull2(f2);
        ulonglong2 D = as_ull2(f3);

        // k=0 via mul (defines acc, no init movs)
        unsigned long long acc0 = mul2(A.x, wpp0[0]);
        unsigned long long acc1 = mul2(A.x, wpp1[0]);
        unsigned long long acc2 = mul2(A.x, wpp2[0]);
        unsigned long long acc3 = mul2(A.x, wpp3[0]);
#define QSTEP(sp2, k)         \
    fma2(acc0, sp2, wpp0[k]); \
    fma2(acc1, sp2, wpp1[k]); \
    fma2(acc2, sp2, wpp2[k]); \
    fma2(acc3, sp2, wpp3[k]);
        QSTEP(A.y, 1)
        QSTEP(B.x, 2)
        QSTEP(B.y, 3)
        QSTEP(C.x, 4)
        QSTEP(C.y, 5)
        QSTEP(D.x, 6)
        QSTEP(D.y, 7)
#undef QSTEP

        const int n = h * 32 + row;
        float* op =
            out + (((size_t)(b * 64 + n) * 64 + (a0 + ai)) * 256) + d0;
        float2 r0 = as_f2(acc0), r1 = as_f2(acc1);
        float2 r2 = as_f2(acc2), r3 = as_f2(acc3);
        __stcs(reinterpret_cast<float4*>(op),
               make_float4(r0.x + r0.y + bias.x, r1.x + r1.y + bias.y,
                           r2.x + r2.y + bias.z, r3.x + r3.y + bias.w));
    }
}

// ============================================================================
extern "C" void kernel_launch(void* const* d_in, const int* in_sizes, int n_in,
                              void* d_out, int out_size) {
    const float* x = (const float*)d_in[0];
    const float* conv_w = (const float*)d_in[1];
    const float* conv_b = (const float*)d_in[2];
    const float* lin_w = (const float*)d_in[3];
    const float* lin_b = (const float*)d_in[4];
    const float* wp_w = (const float*)d_in[5];
    const float* wp_b = (const float*)d_in[6];

    conv_pool_kernel<<<dim3(8, BB), 256>>>(x, conv_w, conv_b);
    patch_kernel<<<dim3(AAA / 2, BB, 2), 256>>>(x, lin_w, lin_b, wp_w, wp_b,
                                                (float*)d_out);
}